// round 17
// baseline (speedup 1.0000x reference)
#include <cuda_runtime.h>
#include <cuda_bf16.h>
#include <cstdint>
#include <math.h>

// Problem dims (fixed by the reference)
#define BB 4
#define LL 4096
#define EE 1024
#define HH 16
#define DD 64
#define BH (BB*HH)       // 64
#define MM (BB*LL)       // 16384
#define LSPLIT 8

// GEMM tiling (bf16 split mma.sync)
#define BM 128
#define BN 128
#define BK 32                         // fp32-equivalent K per stage
#define PITCH 20                      // u32 per smem row (80B): conflict-free + 16B aligned
#define PLANE_U32 (128*PITCH)         // one operand plane (hi or lo): 10240 B
#define STAGE_U32 (4*PLANE_U32)       // Ahi,Alo,Bhi,Blo
#define SMEM_BYTES (2*STAGE_U32*4)    // double buffered = 81920 B
#define GT 512                        // 16 warps: 2 (M) x 8 (N), warp tile 64x16

// kv_state MMA tiling
#define KPITCH 40                     // bf16 per smem row (80B) — same bank rotation
#define KPB 80                        // bytes per row
#define KPLANE (64*KPITCH)            // bf16 units per plane
#define KV_LC (LL/LSPLIT)             // 512 l per split
#define KV_NST (KV_LC/32)             // 16 stages

// ---------------- scratch ---------------------------------------------------
__device__ __nv_bfloat16 g_Xhi[MM*EE], g_Xlo[MM*EE];
__device__ __nv_bfloat16 g_Whi[4][EE*EE], g_Wlo[4][EE*EE];   // q,k,v,o
__device__ __nv_bfloat16 g_Chi[MM*EE], g_Clo[MM*EE];         // ctx split
__device__ __nv_bfloat16 g_KThi[BH*DD*LL], g_KTlo[BH*DD*LL]; // phiK transposed [bh][d][l]
__device__ __nv_bfloat16 g_VThi[BH*DD*LL], g_VTlo[BH*DD*LL]; // V transposed
__device__ float g_phiQ[MM*EE];
__device__ float g_S  [BH*DD*DD];
__device__ float g_Z  [BH*DD];
__device__ float g_Spart[LSPLIT*BH*DD*DD];
__device__ float g_Zpart[LSPLIT*BH*DD];

// ---------------- helpers ---------------------------------------------------
__device__ __forceinline__ void cpasync16(uint32_t dst, const void* src){
    asm volatile("cp.async.cg.shared.global [%0], [%1], 16;" :: "r"(dst), "l"(src) : "memory");
}
__device__ __forceinline__ void cp_commit(){
    asm volatile("cp.async.commit_group;" ::: "memory");
}
template<int N> __device__ __forceinline__ void cp_wait(){
    asm volatile("cp.async.wait_group %0;" :: "n"(N) : "memory");
}
__device__ __forceinline__ uint32_t smem_u32(const void* p){
    uint32_t a;
    asm("{ .reg .u64 t; cvta.to.shared.u64 t, %1; cvt.u32.u64 %0, t; }" : "=r"(a) : "l"(p));
    return a;
}
__device__ __forceinline__ void mma_bf16(float* c, const uint32_t* a, const uint32_t* b){
    asm volatile("mma.sync.aligned.m16n8k16.row.col.f32.bf16.bf16.f32 "
        "{%0,%1,%2,%3}, {%4,%5,%6,%7}, {%8,%9}, {%0,%1,%2,%3};"
        : "+f"(c[0]), "+f"(c[1]), "+f"(c[2]), "+f"(c[3])
        : "r"(a[0]), "r"(a[1]), "r"(a[2]), "r"(a[3]), "r"(b[0]), "r"(b[1]));
}
__device__ __forceinline__ void ldsm_x4(uint32_t* r, uint32_t addr){
    asm volatile("ldmatrix.sync.aligned.m8n8.x4.shared.b16 {%0,%1,%2,%3}, [%4];"
        : "=r"(r[0]), "=r"(r[1]), "=r"(r[2]), "=r"(r[3]) : "r"(addr));
}
__device__ __forceinline__ void bsplit(float x, __nv_bfloat16& h, __nv_bfloat16& l){
    h = __float2bfloat16(x);
    l = __float2bfloat16(x - __bfloat162float(h));
}

// ---------------- fp32 -> bf16 hi/lo split (single merged launch) -----------
// blocks [0,16384): X ; then 4x1024 blocks for Wq,Wk,Wv,Wo
__global__ void __launch_bounds__(256)
split_all_kernel(const float* __restrict__ X,
                 const float* __restrict__ Wq, const float* __restrict__ Wk,
                 const float* __restrict__ Wv, const float* __restrict__ Wo)
{
    int blk = blockIdx.x;
    const float* src;
    __nv_bfloat16 *hi, *lo;
    int base;
    if (blk < 16384) {
        src = X; hi = g_Xhi; lo = g_Xlo; base = blk;
    } else {
        int w  = (blk - 16384) >> 10;
        int rb = (blk - 16384) & 1023;
        src = (w == 0) ? Wq : (w == 1) ? Wk : (w == 2) ? Wv : Wo;
        hi = g_Whi[w]; lo = g_Wlo[w]; base = rb;
    }
    int i = (base * 256 + threadIdx.x) * 4;
    float4 v = *(const float4*)(src + i);
    float x[4] = {v.x, v.y, v.z, v.w};
    uint32_t hp[2], lp[2];
    #pragma unroll
    for (int p = 0; p < 2; p++) {
        __nv_bfloat16 h0, l0, h1, l1;
        bsplit(x[2*p],   h0, l0);
        bsplit(x[2*p+1], h1, l1);
        hp[p] = ((uint32_t)__bfloat16_as_ushort(h1) << 16) | __bfloat16_as_ushort(h0);
        lp[p] = ((uint32_t)__bfloat16_as_ushort(l1) << 16) | __bfloat16_as_ushort(l0);
    }
    *(uint2*)(hi + i) = make_uint2(hp[0], hp[1]);
    *(uint2*)(lo + i) = make_uint2(lp[0], lp[1]);
}

// ---------------- bf16-split tensor-core GEMM body --------------------------
// mode 0: fp32 out; 1: elu+1 fp32 out; 2: elu+1 -> transposed hi/lo; 3: plain -> transposed hi/lo
__device__ __forceinline__ void load_tile(uint32_t st,
                                          const __nv_bfloat16* __restrict__ Ahi,
                                          const __nv_bfloat16* __restrict__ Alo,
                                          const __nv_bfloat16* __restrict__ Bhi,
                                          const __nv_bfloat16* __restrict__ Blo,
                                          int m0, int n0, int k0, int tid)
{
    // 512 threads, one pass: 512 slots = 128 rows x 4 x 16B chunks
    int row = tid >> 2;                // 0..127
    int cg  = tid & 3;                 // 16B chunk within 64B row (32 bf16)
    uint32_t off = (uint32_t)(row * PITCH * 4 + cg * 16);
    size_t ga = (size_t)(m0 + row) * EE + k0 + cg * 8;
    size_t gb = (size_t)(n0 + row) * EE + k0 + cg * 8;
    cpasync16(st + off,                    Ahi + ga);
    cpasync16(st + PLANE_U32*4   + off,    Alo + ga);
    cpasync16(st + 2*PLANE_U32*4 + off,    Bhi + gb);
    cpasync16(st + 3*PLANE_U32*4 + off,    Blo + gb);
}

__device__ __forceinline__ void mma_gemm(const __nv_bfloat16* __restrict__ Ahi,
                                         const __nv_bfloat16* __restrict__ Alo,
                                         const __nv_bfloat16* __restrict__ Bhi,
                                         const __nv_bfloat16* __restrict__ Blo,
                                         const float* __restrict__ bias,
                                         float* __restrict__ C,
                                         __nv_bfloat16* __restrict__ Thi,
                                         __nv_bfloat16* __restrict__ Tlo,
                                         int mode)
{
    extern __shared__ uint32_t smem[];
    const uint32_t sbase = smem_u32(smem);

    const int tid  = threadIdx.x;
    const int wid  = tid >> 5;           // 0..15
    const int lane = tid & 31;
    const int g    = lane >> 2;
    const int tg   = lane & 3;
    const int m0   = blockIdx.y * BM;
    const int n0   = blockIdx.x * BN;
    const int warpM = (wid >> 3) * 64;   // 2 warps in M (64 rows each)
    const int warpN = (wid & 7) * 16;    // 8 warps in N (16 cols each)

    const int a_row = lane & 15;
    const int a_col = (lane >> 4) * 16;
    const int b_row = lane & 7;
    const int b_sel = ((lane >> 3) & 1) * 16;
    const int b_pair = (lane >> 4);

    float acc[4][2][4];                  // [mt][nt][reg]
    #pragma unroll
    for (int i = 0; i < 4; i++)
        #pragma unroll
        for (int j = 0; j < 2; j++)
            #pragma unroll
            for (int r = 0; r < 4; r++) acc[i][j][r] = 0.f;

    load_tile(sbase, Ahi, Alo, Bhi, Blo, m0, n0, 0, tid);
    cp_commit();

    const int NIT = EE / BK;             // 32
    for (int it = 0; it < NIT; it++) {
        cp_wait<0>();                    // current stage (it&1) landed
        __syncthreads();                 // all warps done with prev compute; data visible
        if (it + 1 < NIT) {              // prefetch next stage into the other buffer
            load_tile(sbase + ((it + 1) & 1) * STAGE_U32 * 4,
                      Ahi, Alo, Bhi, Blo, m0, n0, (it + 1) * BK, tid);
            cp_commit();
        }

        const uint32_t stage = sbase + (it & 1) * STAGE_U32 * 4;
        const uint32_t A_hi = stage;
        const uint32_t A_lo = stage + PLANE_U32 * 4;
        const uint32_t B_hi = stage + 2 * PLANE_U32 * 4;
        const uint32_t B_lo = stage + 3 * PLANE_U32 * 4;

        #pragma unroll
        for (int kb = 0; kb < 2; kb++) {
            const uint32_t kbyte = kb * 32;
            uint32_t ah[4][4], al[4][4], bh[2][2], bl[2][2];

            #pragma unroll
            for (int mt = 0; mt < 4; mt++) {
                uint32_t aoff = (uint32_t)(warpM + mt * 16 + a_row) * (PITCH * 4)
                                + kbyte + a_col;
                ldsm_x4(ah[mt], A_hi + aoff);
                ldsm_x4(al[mt], A_lo + aoff);
            }
            {   // one x4 ldmatrix per plane covers both nt (8-col) tiles
                uint32_t boff = (uint32_t)(warpN + b_pair * 8 + b_row) * (PITCH * 4)
                                + kbyte + b_sel;
                uint32_t th[4], tl[4];
                ldsm_x4(th, B_hi + boff);
                ldsm_x4(tl, B_lo + boff);
                bh[0][0] = th[0]; bh[0][1] = th[1];
                bh[1][0] = th[2]; bh[1][1] = th[3];
                bl[0][0] = tl[0]; bl[0][1] = tl[1];
                bl[1][0] = tl[2]; bl[1][1] = tl[3];
            }

            #pragma unroll
            for (int mt = 0; mt < 4; mt++)
                #pragma unroll
                for (int nt = 0; nt < 2; nt++) {
                    mma_bf16(acc[mt][nt], ah[mt], bh[nt]);
                    mma_bf16(acc[mt][nt], ah[mt], bl[nt]);
                    mma_bf16(acc[mt][nt], al[mt], bh[nt]);
                }
        }
    }

    // epilogue
    #pragma unroll
    for (int mt = 0; mt < 4; mt++) {
        int row = m0 + warpM + mt * 16 + g;
        #pragma unroll
        for (int nt = 0; nt < 2; nt++) {
            int col = n0 + warpN + nt * 8 + 2 * tg;
            float b0 = bias[col], b1 = bias[col + 1];
            float v0 = acc[mt][nt][0] + b0;
            float v1 = acc[mt][nt][1] + b1;
            float v2 = acc[mt][nt][2] + b0;
            float v3 = acc[mt][nt][3] + b1;
            if (mode == 1 || mode == 2) {
                v0 = (v0 > 0.f) ? (v0 + 1.f) : expf(v0);
                v1 = (v1 > 0.f) ? (v1 + 1.f) : expf(v1);
                v2 = (v2 > 0.f) ? (v2 + 1.f) : expf(v2);
                v3 = (v3 > 0.f) ? (v3 + 1.f) : expf(v3);
            }
            if (mode <= 1) {
                *(float2*)&C[(size_t)row * EE + col]       = make_float2(v0, v1);
                *(float2*)&C[(size_t)(row + 8) * EE + col] = make_float2(v2, v3);
            } else {
                // transposed bf16 hi/lo: dst[(b*1024 + col)][l], l = row % LL
                int bi = row >> 12;
                int l  = row & (LL - 1);
                size_t p0 = ((size_t)(bi * 1024 + col)) * LL + l;
                size_t p1 = p0 + LL;   // col+1
                __nv_bfloat16 h, lo;
                bsplit(v0, h, lo); Thi[p0]     = h; Tlo[p0]     = lo;
                bsplit(v2, h, lo); Thi[p0 + 8] = h; Tlo[p0 + 8] = lo;
                bsplit(v1, h, lo); Thi[p1]     = h; Tlo[p1]     = lo;
                bsplit(v3, h, lo); Thi[p1 + 8] = h; Tlo[p1 + 8] = lo;
            }
        }
    }
}

// grid (8, 128, 3): z selects Q/K/V
__global__ void __launch_bounds__(GT)
qkv_mma_kernel(const float* __restrict__ bq,
               const float* __restrict__ bk,
               const float* __restrict__ bv)
{
    int z = blockIdx.z;
    if (z == 0)
        mma_gemm(g_Xhi, g_Xlo, g_Whi[0], g_Wlo[0], bq, g_phiQ, nullptr, nullptr, 1);
    else if (z == 1)
        mma_gemm(g_Xhi, g_Xlo, g_Whi[1], g_Wlo[1], bk, nullptr, g_KThi, g_KTlo, 2);
    else
        mma_gemm(g_Xhi, g_Xlo, g_Whi[2], g_Wlo[2], bv, nullptr, g_VThi, g_VTlo, 3);
}

__global__ void __launch_bounds__(GT)
out_mma_kernel(const float* __restrict__ bo, float* __restrict__ out)
{
    mma_gemm(g_Chi, g_Clo, g_Whi[3], g_Wlo[3], bo, out, nullptr, nullptr, 0);
}

// ---------------- KV state on tensor cores ----------------------------------
// S_part[bh][i][j] = sum_{l in split} phiK[l,i] * V[l,j], via transposed hi/lo planes.
__global__ void __launch_bounds__(128)
kv_state_mma_kernel()
{
    __shared__ __nv_bfloat16 sm[2][4 * KPLANE];

    const int bh  = blockIdx.x;
    const int p   = blockIdx.y;
    const int tid = threadIdx.x;
    const int wid = tid >> 5;
    const int lane = tid & 31;
    const int g   = lane >> 2;
    const int tg  = lane & 3;
    const int a_row = lane & 15;
    const int a_col = (lane >> 4) * 16;
    const int b_row = lane & 7;
    const int b_sel = ((lane >> 3) & 1) * 16;
    const int b_pair = lane >> 4;

    const size_t gbase = (size_t)bh * DD * LL + (size_t)p * KV_LC;
    const __nv_bfloat16* srcs[4] = { g_KThi + gbase, g_KTlo + gbase,
                                     g_VThi + gbase, g_VTlo + gbase };

    float acc[4][2][4];
    #pragma unroll
    for (int i = 0; i < 4; i++)
        #pragma unroll
        for (int j = 0; j < 2; j++)
            #pragma unroll
            for (int r = 0; r < 4; r++) acc[i][j][r] = 0.f;
    float zacc = 0.f;

    auto issue_load = [&](int buf, int s){
        uint32_t dst0 = smem_u32(&sm[buf][0]);
        int l0 = s * 32;
        #pragma unroll
        for (int t = 0; t < 8; t++) {
            int q = tid + 128 * t;           // 0..1023
            int plane = q >> 8;
            int rem = q & 255;
            int row = rem >> 2;
            int cg = rem & 3;
            const __nv_bfloat16* src = srcs[plane] + (size_t)row * LL + l0 + cg * 8;
            uint32_t dst = dst0 + (uint32_t)(plane * KPLANE + row * KPITCH + cg * 8) * 2;
            cpasync16(dst, src);
        }
    };

    issue_load(0, 0);
    cp_commit();

    for (int s = 0; s < KV_NST; s++) {
        cp_wait<0>();
        __syncthreads();
        if (s + 1 < KV_NST) {
            issue_load((s + 1) & 1, s + 1);
            cp_commit();
        }

        uint32_t sb = smem_u32(&sm[s & 1][0]);
        uint32_t Khi = sb;
        uint32_t Klo = sb + KPLANE * 2;
        uint32_t Vhi = sb + 2 * KPLANE * 2;
        uint32_t Vlo = sb + 3 * KPLANE * 2;

        #pragma unroll
        for (int kb = 0; kb < 2; kb++) {
            uint32_t kbyte = kb * 32;
            uint32_t ah[4][4], al[4][4], bhf[2][2], blf[2][2];
            #pragma unroll
            for (int mt = 0; mt < 4; mt++) {
                uint32_t aoff = (uint32_t)(mt * 16 + a_row) * KPB + kbyte + a_col;
                ldsm_x4(ah[mt], Khi + aoff);
                ldsm_x4(al[mt], Klo + aoff);
            }
            uint32_t boff = (uint32_t)(wid * 16 + b_pair * 8 + b_row) * KPB + kbyte + b_sel;
            uint32_t th[4], tl[4];
            ldsm_x4(th, Vhi + boff);
            ldsm_x4(tl, Vlo + boff);
            bhf[0][0] = th[0]; bhf[0][1] = th[1];
            bhf[1][0] = th[2]; bhf[1][1] = th[3];
            blf[0][0] = tl[0]; blf[0][1] = tl[1];
            blf[1][0] = tl[2]; blf[1][1] = tl[3];

            #pragma unroll
            for (int mt = 0; mt < 4; mt++)
                #pragma unroll
                for (int nt = 0; nt < 2; nt++) {
                    mma_bf16(acc[mt][nt], ah[mt], bhf[nt]);
                    mma_bf16(acc[mt][nt], ah[mt], blf[nt]);
                    mma_bf16(acc[mt][nt], al[mt], bhf[nt]);
                }
        }

        // deterministic Z partial: threads 0..63 sum phiK row d over this stage
        if (tid < DD) {
            const __nv_bfloat16* kh = &sm[s & 1][tid * KPITCH];
            const __nv_bfloat16* kl = kh + KPLANE;
            #pragma unroll
            for (int i = 0; i < 32; i++)
                zacc += __bfloat162float(kh[i]) + __bfloat162float(kl[i]);
        }
    }

    float* Sp = g_Spart + ((size_t)p * BH + bh) * DD * DD;
    #pragma unroll
    for (int mt = 0; mt < 4; mt++) {
        int m = mt * 16 + g;
        #pragma unroll
        for (int nt = 0; nt < 2; nt++) {
            int n = wid * 16 + nt * 8 + 2 * tg;
            *(float2*)&Sp[m * DD + n]       = make_float2(acc[mt][nt][0], acc[mt][nt][1]);
            *(float2*)&Sp[(m + 8) * DD + n] = make_float2(acc[mt][nt][2], acc[mt][nt][3]);
        }
    }
    if (tid < DD)
        g_Zpart[((size_t)p * BH + bh) * DD + tid] = zacc;
}

__global__ void __launch_bounds__(256)
reduce_kernel()
{
    int idx = blockIdx.x * 256 + threadIdx.x;
    if (idx < BH * DD * DD) {
        float s = 0.f;
        #pragma unroll
        for (int pp = 0; pp < LSPLIT; pp++) s += g_Spart[(size_t)pp * BH * DD * DD + idx];
        g_S[idx] = s;
    }
    if (idx < BH * DD) {
        float s = 0.f;
        #pragma unroll
        for (int pp = 0; pp < LSPLIT; pp++) s += g_Zpart[(size_t)pp * BH * DD + idx];
        g_Z[idx] = s;
    }
}

// ---------------- context = (phiQ @ S) / (phiQ . Z + eps) --------------------
// writes ctx directly as bf16 hi/lo planes for the out-projection GEMM.
__global__ void __launch_bounds__(256)
attn_out_kernel()
{
    __shared__ float Ss[DD][68];
    __shared__ float Qt[DD][68];   // Qt[k][l] (transposed)
    __shared__ float Zs[DD];

    const int bh = blockIdx.x;
    const int b  = bh >> 4, h = bh & 15;
    const int l0 = blockIdx.y * 64;
    const int tid = threadIdx.x;

    const float* Sp = g_S + (size_t)bh * DD * DD;
    const float* Qp = g_phiQ + (size_t)b * LL * EE + h * DD;

    for (int idx = tid; idx < DD * DD; idx += 256) {
        int r = idx >> 6, c = idx & 63;
        Ss[r][c] = Sp[idx];
        Qt[c][r] = Qp[(size_t)(l0 + r) * EE + c];
    }
    if (tid < DD) Zs[tid] = g_Z[bh * DD + tid];
    __syncthreads();

    const int tx = tid & 15, ty = tid >> 4;
    float num[4][4];
    float den[4] = {0.f, 0.f, 0.f, 0.f};
    #pragma unroll
    for (int i = 0; i < 4; i++)
        #pragma unroll
        for (int j = 0; j < 4; j++) num[i][j] = 0.f;

    #pragma unroll 8
    for (int k = 0; k < DD; k++) {
        float4 q = *(const float4*)&Qt[k][ty * 4];
        float4 s = *(const float4*)&Ss[k][tx * 4];
        float  z = Zs[k];
        float qa[4] = {q.x, q.y, q.z, q.w};
        float sa[4] = {s.x, s.y, s.z, s.w};
        #pragma unroll
        for (int i = 0; i < 4; i++) {
            #pragma unroll
            for (int j = 0; j < 4; j++) num[i][j] += qa[i] * sa[j];
            den[i] += qa[i] * z;
        }
    }

    #pragma unroll
    for (int i = 0; i < 4; i++) {
        float inv = 1.f / (den[i] + 1e-6f);
        uint32_t hp[2], lp[2];
        #pragma unroll
        for (int p = 0; p < 2; p++) {
            float x0 = num[i][2*p]   * inv;
            float x1 = num[i][2*p+1] * inv;
            __nv_bfloat16 h0, l0v, h1, l1v;
            bsplit(x0, h0, l0v);
            bsplit(x1, h1, l1v);
            hp[p] = ((uint32_t)__bfloat16_as_ushort(h1) << 16) | __bfloat16_as_ushort(h0);
            lp[p] = ((uint32_t)__bfloat16_as_ushort(l1v) << 16) | __bfloat16_as_ushort(l0v);
        }
        size_t idx = (size_t)(b * LL + l0 + ty * 4 + i) * EE + h * DD + tx * 4;
        *(uint2*)(g_Chi + idx) = make_uint2(hp[0], hp[1]);
        *(uint2*)(g_Clo + idx) = make_uint2(lp[0], lp[1]);
    }
}

// ---------------------------------------------------------------------------
extern "C" void kernel_launch(void* const* d_in, const int* in_sizes, int n_in,
                              void* d_out, int out_size)
{
    const float* X  = (const float*)d_in[0];
    const float* Wq = (const float*)d_in[1];
    const float* bq = (const float*)d_in[2];
    const float* Wk = (const float*)d_in[3];
    const float* bk = (const float*)d_in[4];
    const float* Wv = (const float*)d_in[5];
    const float* bv = (const float*)d_in[6];
    const float* Wo = (const float*)d_in[7];
    const float* bo = (const float*)d_in[8];
    float* out = (float*)d_out;

    cudaFuncSetAttribute(qkv_mma_kernel, cudaFuncAttributeMaxDynamicSharedMemorySize, SMEM_BYTES);
    cudaFuncSetAttribute(out_mma_kernel, cudaFuncAttributeMaxDynamicSharedMemorySize, SMEM_BYTES);

    // one merged split launch: X + 4 weight matrices
    split_all_kernel<<<16384 + 4 * 1024, 256>>>(X, Wq, Wk, Wv, Wo);

    dim3 gqkv(EE / BN, MM / BM, 3);
    qkv_mma_kernel<<<gqkv, GT, SMEM_BYTES>>>(bq, bk, bv);

    kv_state_mma_kernel<<<dim3(BH, LSPLIT), 128>>>();
    reduce_kernel<<<(BH * DD * DD + 255) / 256, 256>>>();
    attn_out_kernel<<<dim3(BH, LL / 64), 256>>>();

    dim3 gout(EE / BN, MM / BM, 1);
    out_mma_kernel<<<gout, GT, SMEM_BYTES>>>(bo, out);
}